// round 10
// baseline (speedup 1.0000x reference)
#include <cuda_runtime.h>
#include <cstdint>

// GatherBlock: out[m, :, :, :] = x[b[m], :, yb[m]*16 : yb[m]*16+16, xb[m]*16 : xb[m]*16+16]
// x: (8, 64, 256, 256) fp32, indices: (1024, 3) int32, out: (1024, 64, 16, 16) fp32.
//
// R10: max in-flight-bytes corner of the config space: SPLIT=2 (2048 CTAs x
// 32KB), 256 threads x 8 front-batched LDG.128 => ~256KB in flight/SM at 8
// resident CTAs (vs 192KB best so far). Keep counting-sort tile-ordered
// schedule (~free), __ldcg read-once loads (L2 still dedups duplicate tiles),
// __stcs streaming stores.

static constexpr int C = 64;
static constexpr int H = 256;
static constexpr int W = 256;
static constexpr int BH = 16;
static constexpr int BW = 16;
static constexpr int CHW = C * H * W;      // 4194304
static constexpr int HW = H * W;           // 65536
static constexpr int VEC_PER_M = C * BH * BW / 4;     // 4096 float4 per output block
static constexpr int SPLIT = 2;                       // CTAs per m
static constexpr int VEC_PER_CTA = VEC_PER_M / SPLIT; // 2048 float4 per CTA
static constexpr int M_MAX = 1024;
static constexpr int BINS = 2048;                     // 8*16*16 tile ids
static constexpr int TPB = 256;                       // threads per gather CTA
static constexpr int LPT = VEC_PER_CTA / TPB;         // 8 float4 per thread

__device__ int g_perm[M_MAX];

__global__ __launch_bounds__(M_MAX, 1)
void sort_indices_kernel(const int* __restrict__ idx, int M)
{
    __shared__ unsigned hist[BINS];
    __shared__ unsigned warpsum[32];

    const int t = threadIdx.x;
    const int lane = t & 31;
    const int wid = t >> 5;

    hist[2 * t]     = 0;
    hist[2 * t + 1] = 0;
    __syncthreads();

    int key = 0;
    if (t < M) {
        const int b  = idx[3 * t + 0];
        const int yb = idx[3 * t + 1];
        const int xb = idx[3 * t + 2];
        key = (b << 8) | (yb << 4) | xb;   // 11 bits
        atomicAdd(&hist[key], 1u);
    }
    __syncthreads();

    const unsigned a = hist[2 * t];
    const unsigned bcnt = hist[2 * t + 1];
    const unsigned s = a + bcnt;

    unsigned incl = s;
#pragma unroll
    for (int d = 1; d < 32; d <<= 1) {
        const unsigned n = __shfl_up_sync(0xFFFFFFFFu, incl, d);
        if (lane >= d) incl += n;
    }
    const unsigned thr_excl = incl - s;
    if (lane == 31) warpsum[wid] = incl;
    __syncthreads();

    if (wid == 0) {
        unsigned v = warpsum[lane];
        unsigned pv = v;
#pragma unroll
        for (int d = 1; d < 32; d <<= 1) {
            const unsigned n = __shfl_up_sync(0xFFFFFFFFu, pv, d);
            if (lane >= d) pv += n;
        }
        warpsum[lane] = pv - v;
    }
    __syncthreads();

    const unsigned base = warpsum[wid] + thr_excl;
    hist[2 * t]     = base;
    hist[2 * t + 1] = base + a;
    __syncthreads();

    if (t < M) {
        const unsigned pos = atomicAdd(&hist[key], 1u);
        g_perm[pos] = t;
    }
}

__global__ __launch_bounds__(TPB, 8)
void gather_block_kernel(const float* __restrict__ x,
                         const int* __restrict__ idx,
                         float4* __restrict__ out)
{
    const int m = g_perm[blockIdx.x >> 1];  // tile-address-sorted order
    const int q = blockIdx.x & 1;           // which half of the block

    const int b  = idx[3 * m + 0];
    const int yb = idx[3 * m + 1];
    const int xb = idx[3 * m + 2];

    // base of the gathered tile: x[b, 0, yb*16, xb*16]
    const float* src = x + (size_t)b * CHW + (size_t)(yb * BH) * W + (size_t)(xb * BW);
    float4* dst = out + (size_t)m * VEC_PER_M;

    const int t = threadIdx.x;
    const int v0 = q * VEC_PER_CTA + t;     // starting float4 index within the block

    // v in [0, 4096): c = v>>6, row i = (v>>2)&15, j-vector = v&3.
    // Front-batch all 8 loads (max bytes in flight), then stream-store.
    float4 r[LPT];
#pragma unroll
    for (int k = 0; k < LPT; k++) {
        const int v = v0 + k * TPB;
        const int c = v >> 6;
        const int i = (v >> 2) & 15;
        const int j = v & 3;
        const float4* s = reinterpret_cast<const float4*>(
            src + (size_t)c * HW + (size_t)i * W) + j;
        r[k] = __ldcg(s);
    }
#pragma unroll
    for (int k = 0; k < LPT; k++) {
        __stcs(dst + v0 + k * TPB, r[k]);
    }
}

extern "C" void kernel_launch(void* const* d_in, const int* in_sizes, int n_in,
                              void* d_out, int out_size)
{
    const float* x  = (const float*)d_in[0];
    const int* idx  = (const int*)d_in[1];
    float4* out     = (float4*)d_out;

    const int M = in_sizes[1] / 3;  // 1024
    sort_indices_kernel<<<1, M_MAX>>>(idx, M);
    gather_block_kernel<<<M * SPLIT, TPB>>>(x, idx, out);
}

// round 11
// speedup vs baseline: 1.2087x; 1.2087x over previous
#include <cuda_runtime.h>
#include <cstdint>

// GatherBlock: out[m, :, :, :] = x[b[m], :, yb[m]*16 : yb[m]*16+16, xb[m]*16 : xb[m]*16+16]
// x: (8, 64, 256, 256) fp32, indices: (1024, 3) int32, out: (1024, 64, 16, 16) fp32.
//
// R11: gather kernel is at the mixed-stream DRAM floor (~22.5us across all
// configs); remaining bench time is launch overhead. Use PDL: the gather is
// launched with programmatic-stream-serialization and blocks in-SM on
// cudaGridDependencySynchronize() until the counting-sort kernel completes
// (default trigger => perm writes visible), hiding the second node's launch
// latency. Gather config = best measured (R8): SPLIT=4, 128 thr x 8
// front-batched LDG.128, __ldcg reads, __stcs streaming stores, tile-sorted
// CTA order.

static constexpr int C = 64;
static constexpr int H = 256;
static constexpr int W = 256;
static constexpr int BH = 16;
static constexpr int BW = 16;
static constexpr int CHW = C * H * W;      // 4194304
static constexpr int HW = H * W;           // 65536
static constexpr int VEC_PER_M = C * BH * BW / 4;     // 4096 float4 per output block
static constexpr int SPLIT = 4;                       // CTAs per m
static constexpr int VEC_PER_CTA = VEC_PER_M / SPLIT; // 1024 float4 per CTA
static constexpr int M_MAX = 1024;
static constexpr int BINS = 2048;                     // 8*16*16 tile ids
static constexpr int TPB = 128;                       // threads per gather CTA
static constexpr int LPT = VEC_PER_CTA / TPB;         // 8 float4 per thread

__device__ int g_perm[M_MAX];

__global__ __launch_bounds__(M_MAX, 1)
void sort_indices_kernel(const int* __restrict__ idx, int M)
{
    __shared__ unsigned hist[BINS];
    __shared__ unsigned warpsum[32];

    const int t = threadIdx.x;
    const int lane = t & 31;
    const int wid = t >> 5;

    hist[2 * t]     = 0;
    hist[2 * t + 1] = 0;
    __syncthreads();

    int key = 0;
    if (t < M) {
        const int b  = idx[3 * t + 0];
        const int yb = idx[3 * t + 1];
        const int xb = idx[3 * t + 2];
        key = (b << 8) | (yb << 4) | xb;   // 11 bits
        atomicAdd(&hist[key], 1u);
    }
    __syncthreads();

    const unsigned a = hist[2 * t];
    const unsigned bcnt = hist[2 * t + 1];
    const unsigned s = a + bcnt;

    unsigned incl = s;
#pragma unroll
    for (int d = 1; d < 32; d <<= 1) {
        const unsigned n = __shfl_up_sync(0xFFFFFFFFu, incl, d);
        if (lane >= d) incl += n;
    }
    const unsigned thr_excl = incl - s;
    if (lane == 31) warpsum[wid] = incl;
    __syncthreads();

    if (wid == 0) {
        unsigned v = warpsum[lane];
        unsigned pv = v;
#pragma unroll
        for (int d = 1; d < 32; d <<= 1) {
            const unsigned n = __shfl_up_sync(0xFFFFFFFFu, pv, d);
            if (lane >= d) pv += n;
        }
        warpsum[lane] = pv - v;
    }
    __syncthreads();

    const unsigned base = warpsum[wid] + thr_excl;
    hist[2 * t]     = base;
    hist[2 * t + 1] = base + a;
    __syncthreads();

    if (t < M) {
        const unsigned pos = atomicAdd(&hist[key], 1u);
        g_perm[pos] = t;
    }
}

__global__ __launch_bounds__(TPB)
void gather_block_kernel(const float* __restrict__ x,
                         const int* __restrict__ idx,
                         float4* __restrict__ out)
{
    // PDL: wait for the sort kernel (and its memory flush) before reading
    // g_perm. The grid itself launched concurrently with the sort.
    cudaGridDependencySynchronize();

    const int m = g_perm[blockIdx.x >> 2];  // tile-address-sorted order
    const int q = blockIdx.x & 3;           // which quarter of the block

    const int b  = idx[3 * m + 0];
    const int yb = idx[3 * m + 1];
    const int xb = idx[3 * m + 2];

    // base of the gathered tile: x[b, 0, yb*16, xb*16]
    const float* src = x + (size_t)b * CHW + (size_t)(yb * BH) * W + (size_t)(xb * BW);
    float4* dst = out + (size_t)m * VEC_PER_M;

    const int t = threadIdx.x;
    const int v0 = q * VEC_PER_CTA + t;     // starting float4 index within the block

    // v in [0, 4096): c = v>>6, row i = (v>>2)&15, j-vector = v&3.
    float4 r[LPT];
#pragma unroll
    for (int k = 0; k < LPT; k++) {
        const int v = v0 + k * TPB;
        const int c = v >> 6;
        const int i = (v >> 2) & 15;
        const int j = v & 3;
        const float4* s = reinterpret_cast<const float4*>(
            src + (size_t)c * HW + (size_t)i * W) + j;
        r[k] = __ldcg(s);
    }
#pragma unroll
    for (int k = 0; k < LPT; k++) {
        __stcs(dst + v0 + k * TPB, r[k]);
    }
}

extern "C" void kernel_launch(void* const* d_in, const int* in_sizes, int n_in,
                              void* d_out, int out_size)
{
    const float* x  = (const float*)d_in[0];
    const int* idx  = (const int*)d_in[1];
    float4* out     = (float4*)d_out;

    const int M = in_sizes[1] / 3;  // 1024

    sort_indices_kernel<<<1, M_MAX>>>(idx, M);

    // Launch gather with programmatic dependent launch: it may begin while
    // the sort is still running; it self-synchronizes in-kernel.
    cudaLaunchConfig_t cfg = {};
    cfg.gridDim = dim3(M * SPLIT, 1, 1);
    cfg.blockDim = dim3(TPB, 1, 1);
    cfg.dynamicSmemBytes = 0;
    cfg.stream = 0;
    cudaLaunchAttribute attrs[1];
    attrs[0].id = cudaLaunchAttributeProgrammaticStreamSerialization;
    attrs[0].val.programmaticStreamSerializationAllowed = 1;
    cfg.attrs = attrs;
    cfg.numAttrs = 1;
    cudaLaunchKernelEx(&cfg, gather_block_kernel, x, idx, out);
}